// round 6
// baseline (speedup 1.0000x reference)
#include <cuda_runtime.h>
#include <math.h>

#define H 4096
#define HS 64
#define NH 64
#define TM 64
#define TD 128

// ---------------- scratch (device globals) ----------------
__device__ float g_xn[H];
__device__ float g_sx[H];
__device__ float g_maa_part[128][5 * TM];     // 128 chunks x 320
__device__ float g_m[5][H];                   // mw, mk, mv, mr, mg
__device__ float g_wd1_part[64][TD];          // 64 splits x 128
__device__ float g_rkvg[4][H];                // r, k, v, g(silu)
__device__ float g_gx[H];

// ---------------- K2: LN1 (redundant per block) + token shift + maa1 GEMV partials ----
__global__ void k2_ln_maa1(const float* __restrict__ x,
                           const float* __restrict__ s1,
                           const float* __restrict__ ln1_w,
                           const float* __restrict__ ln1_b,
                           const float* __restrict__ tmx,
                           const float* __restrict__ Wmaa1,
                           float* __restrict__ d_out) {
    __shared__ float ssum[320], ssq[320];
    __shared__ float sv[32];
    __shared__ float s_mean, s_rs;
    int t = threadIdx.x;
    int c = blockIdx.x;

    float lsum = 0.f, lsq = 0.f;
    const float4* x4 = reinterpret_cast<const float4*>(x);
    for (int i = t; i < 1024; i += 320) {
        float4 v = x4[i];
        lsum += v.x + v.y + v.z + v.w;
        lsq += v.x * v.x + v.y * v.y + v.z * v.z + v.w * v.w;
    }
    ssum[t] = lsum; ssq[t] = lsq;
    __syncthreads();
    if (t < 64) {
        float a = ssum[t], b = ssq[t];
        for (int i = t + 64; i < 320; i += 64) { a += ssum[i]; b += ssq[i]; }
        ssum[t] = a; ssq[t] = b;
    }
    __syncthreads();
    if (t < 32) { ssum[t] += ssum[t + 32]; ssq[t] += ssq[t + 32]; }
    __syncthreads();
    if (t < 16) { ssum[t] += ssum[t + 16]; ssq[t] += ssq[t + 16]; }
    __syncthreads();
    if (t < 8) { ssum[t] += ssum[t + 8]; ssq[t] += ssq[t + 8]; }
    __syncthreads();
    if (t < 4) { ssum[t] += ssum[t + 4]; ssq[t] += ssq[t + 4]; }
    __syncthreads();
    if (t == 0) {
        float su = ssum[0] + ssum[1] + ssum[2] + ssum[3];
        float sq = ssq[0] + ssq[1] + ssq[2] + ssq[3];
        float mean = su * (1.0f / H);
        float var = sq * (1.0f / H) - mean * mean;
        s_mean = mean;
        s_rs = rsqrtf(var + 1e-5f);
    }
    __syncthreads();
    float mean = s_mean, rs = s_rs;

    if (t < 32) {
        int i = c * 32 + t;
        float xn = (x[i] - mean) * rs * ln1_w[i] + ln1_b[i];
        float sx = s1[i] - xn;
        sv[t] = xn + sx * tmx[i];
    }
    if (c < 4) {
        for (int j = t; j < 1024; j += 320) {
            int i = c * 1024 + j;
            float xn = (x[i] - mean) * rs * ln1_w[i] + ln1_b[i];
            float sx = s1[i] - xn;
            g_xn[i] = xn;
            g_sx[i] = sx;
            d_out[H + i] = xn;      // state1_out
        }
    }
    __syncthreads();

    float acc = 0.f;
#pragma unroll 8
    for (int i = 0; i < 32; i++)
        acc += sv[i] * Wmaa1[(size_t)(c * 32 + i) * 320 + t];
    g_maa_part[c][t] = acc;
}

// ---------------- K3: mix = tanh(reduce), m = xn + sx*(mix@W_maa2 + maa) ----------------
__global__ void k3_mix(const float* __restrict__ Wmaa2,
                       const float* __restrict__ maa_w,
                       const float* __restrict__ maa_k,
                       const float* __restrict__ maa_v,
                       const float* __restrict__ maa_r,
                       const float* __restrict__ maa_g) {
    __shared__ float mixs[TM];
    int s = blockIdx.y;
    int t = threadIdx.x;
    if (t < TM) {
        float a = 0.f;
#pragma unroll 8
        for (int cc = 0; cc < 128; cc++) a += g_maa_part[cc][s * TM + t];
        mixs[t] = tanhf(a);
    }
    __syncthreads();
    int h = blockIdx.x * 256 + t;
    float acc = 0.f;
#pragma unroll 8
    for (int e = 0; e < TM; e++)
        acc += mixs[e] * Wmaa2[(size_t)(s * TM + e) * H + h];
    const float* maa = (s == 0) ? maa_w : (s == 1) ? maa_k : (s == 2) ? maa_v
                      : (s == 3) ? maa_r : maa_g;
    g_m[s][h] = g_xn[h] + g_sx[h] * (acc + maa[h]);
}

// ---------------- helpers ----------------
__device__ __forceinline__ void f4_fma(float4& a, float m, const float4& w) {
    a.x += m * w.x; a.y += m * w.y; a.z += m * w.z; a.w += m * w.w;
}
__device__ __forceinline__ void f4_add(float4& a, const float4& b) {
    a.x += b.x; a.y += b.y; a.z += b.z; a.w += b.w;
}

// ---------------- K4: direct full-K GEMV for r/k/v/g (+ Wd1 partials) ----------------
// grid (64, 5), 512 threads.
// y<4: block owns 64 float cols (16 float4). cg = t&15, rg = t>>4 (32 row-groups).
//      Loops 16 tiles of 256 rows; in-block reduce; writes g_rkvg (silu on mat 3).
// y==4: Wd1 split partials: split = blockIdx.x, 4 segs x 128 cols.
__global__ void k4_big(const float* __restrict__ Wr,
                       const float* __restrict__ Wk,
                       const float* __restrict__ Wv,
                       const float* __restrict__ Wg,
                       const float* __restrict__ Wd1) {
    int mat = blockIdx.y;
    int t = threadIdx.x;

    if (mat < 4) {
        __shared__ float sv[256];
        __shared__ float4 sred[512];
        int stripe = blockIdx.x;          // 64 stripes of 16 float4 cols
        int cg = t & 15;
        int rg = t >> 4;                  // 0..31
        const float* vec = (mat == 0) ? g_m[3] : (mat == 1) ? g_m[1]
                          : (mat == 2) ? g_m[2] : g_m[4];
        const float* W = (mat == 0) ? Wr : (mat == 1) ? Wk : (mat == 2) ? Wv : Wg;
        const float4* W4 = reinterpret_cast<const float4*>(W);
        int colbase = stripe * 16 + cg;

        float4 acc = make_float4(0.f, 0.f, 0.f, 0.f);
        for (int tile = 0; tile < 16; tile++) {
            __syncthreads();
            if (t < 256) sv[t] = vec[tile * 256 + t];
            __syncthreads();
#pragma unroll
            for (int i = 0; i < 8; i++) {
                int rr = rg + i * 32;
                f4_fma(acc, sv[rr], W4[(size_t)(tile * 256 + rr) * 1024 + colbase]);
            }
        }
        sred[rg * 16 + cg] = acc;
        __syncthreads();
        for (int s = 16; s > 0; s >>= 1) {
            if (rg < s) f4_add(sred[rg * 16 + cg], sred[(rg + s) * 16 + cg]);
            __syncthreads();
        }
        if (rg == 0) {
            float4 v = sred[cg];
            if (mat == 3) {
                v.x = v.x / (1.0f + expf(-v.x));
                v.y = v.y / (1.0f + expf(-v.y));
                v.z = v.z / (1.0f + expf(-v.z));
                v.w = v.w / (1.0f + expf(-v.w));
            }
            reinterpret_cast<float4*>(g_rkvg[mat])[colbase] = v;
        }
    } else {
        __shared__ float svv[64];
        __shared__ float swd[512];
        int split = blockIdx.x;           // 64 splits of 64 rows
        if (t < 64) svv[t] = g_m[0][split * 64 + t];
        __syncthreads();
        int col = t & 127;
        int seg = t >> 7;                 // 0..3, 16 rows each
        float acc = 0.f;
#pragma unroll
        for (int i = seg * 16; i < seg * 16 + 16; i++)
            acc += svv[i] * Wd1[(size_t)(split * 64 + i) * TD + col];
        swd[t] = acc;
        __syncthreads();
        if (t < TD)
            g_wd1_part[split][t] = swd[t] + swd[t + 128] + swd[t + 256] + swd[t + 384];
    }
}

// ---------------- K7: decay (wd1 reduce + tanh + Wd2 stripe) + heads + instnorm + gate --
// 64 blocks x 256 threads.
__global__ void k7_heads(const float* __restrict__ state2,
                         const float* __restrict__ faaaa,
                         const float* __restrict__ lnx_w,
                         const float* __restrict__ lnx_b,
                         const float* __restrict__ time_decay,
                         const float* __restrict__ Wd2,
                         float* __restrict__ d_out) {
    __shared__ float sdd[TD];
    __shared__ float comb[256];
    __shared__ float r_s[HS], k_s[HS], v_s[HS], td_s[HS];
    __shared__ float prod[HS], part[4 * HS], red[HS], red2[HS];
    int h = blockIdx.x;
    int t = threadIdx.x;
    int base = h * HS;

    // Phase A: reduce g_wd1_part -> tanh -> sdd (redundant per block; L2-hot)
    {
        int col = t & 127, sg = t >> 7;   // 2 segs of 32 splits
        float a = 0.f;
#pragma unroll 8
        for (int s = sg * 32; s < sg * 32 + 32; s++) a += g_wd1_part[s][col];
        comb[t] = a;
    }
    __syncthreads();
    if (t < TD) sdd[t] = tanhf(comb[t] + comb[t + 128]);
    __syncthreads();

    // Phase B: td for this head's 64 cols: Wd2[128][4096] column stripe
    {
        int d = t & 63, sg = t >> 6;      // 4 segs of 32 rows
        float a = 0.f;
#pragma unroll 8
        for (int e = sg * 32; e < sg * 32 + 32; e++)
            a += sdd[e] * Wd2[(size_t)e * H + base + d];
        comb[t] = a;
    }
    __syncthreads();
    if (t < 64) {
        float s = comb[t] + comb[t + 64] + comb[t + 128] + comb[t + 192];
        td_s[t] = expf(-expf(time_decay[base + t] + s));
        float rv = g_rkvg[0][base + t];
        float kv = g_rkvg[1][base + t];
        r_s[t] = rv;
        k_s[t] = kv;
        v_s[t] = g_rkvg[2][base + t];
        prod[t] = rv * kv * faaaa[base + t];
    }
    __syncthreads();
    if (t < 32) prod[t] += prod[t + 32];
    __syncthreads();
    if (t < 16) prod[t] += prod[t + 16];
    __syncthreads();
    if (t < 8) prod[t] += prod[t + 8];
    __syncthreads();
    if (t < 4) prod[t] += prod[t + 4];
    __syncthreads();
    if (t < 2) prod[t] += prod[t + 2];
    __syncthreads();
    if (t == 0) prod[0] += prod[1];
    __syncthreads();
    float dot1 = prod[0];

    int d = t & 63;
    int q = t >> 6;
    const float* s2 = state2 + (size_t)h * HS * HS;
    float* s2o = d_out + 2 * H + (size_t)h * HS * HS;
    float vv = v_s[d];
    float acc = 0.f;
#pragma unroll
    for (int kk = q * 16; kk < q * 16 + 16; kk++) {
        float s2v = s2[kk * HS + d];
        acc += r_s[kk] * s2v;
        s2o[kk * HS + d] = k_s[kk] * vv + s2v * td_s[kk];
    }
    part[q * HS + d] = acc;
    __syncthreads();

    if (t < 64) {
        float out_d = v_s[t] * dot1 + part[t] + part[HS + t] + part[2 * HS + t] + part[3 * HS + t];
        red[t] = out_d;
        red2[t] = out_d * out_d;
        part[t] = out_d;
    }
    __syncthreads();
    if (t < 32) { red[t] += red[t + 32]; red2[t] += red2[t + 32]; }
    __syncthreads();
    if (t < 16) { red[t] += red[t + 16]; red2[t] += red2[t + 16]; }
    __syncthreads();
    if (t < 8) { red[t] += red[t + 8]; red2[t] += red2[t + 8]; }
    __syncthreads();
    if (t < 4) { red[t] += red[t + 4]; red2[t] += red2[t + 4]; }
    __syncthreads();
    if (t < 2) { red[t] += red[t + 2]; red2[t] += red2[t + 2]; }
    __syncthreads();
    if (t == 0) { red[0] += red[1]; red2[0] += red2[1]; }
    __syncthreads();
    if (t < 64) {
        float mean = red[0] * (1.0f / HS);
        float var = red2[0] * (1.0f / HS) - mean * mean;
        float o = (part[t] - mean) * rsqrtf(var + 1e-5f) * lnx_w[base + t] + lnx_b[base + t];
        g_gx[base + t] = o * g_rkvg[3][base + t];
    }
}

// ---------------- K8: direct full-K Wo GEMV + residual ----------------
// 64 blocks x 512 threads, same structure as k4 mats.
__global__ void k8_wo(const float* __restrict__ Wo,
                      const float* __restrict__ x,
                      float* __restrict__ d_out) {
    __shared__ float sv[256];
    __shared__ float4 sred[512];
    int stripe = blockIdx.x;
    int t = threadIdx.x;
    int cg = t & 15;
    int rg = t >> 4;
    const float4* W4 = reinterpret_cast<const float4*>(Wo);
    int colbase = stripe * 16 + cg;

    float4 acc = make_float4(0.f, 0.f, 0.f, 0.f);
    for (int tile = 0; tile < 16; tile++) {
        __syncthreads();
        if (t < 256) sv[t] = g_gx[tile * 256 + t];
        __syncthreads();
#pragma unroll
        for (int i = 0; i < 8; i++) {
            int rr = rg + i * 32;
            f4_fma(acc, sv[rr], W4[(size_t)(tile * 256 + rr) * 1024 + colbase]);
        }
    }
    sred[rg * 16 + cg] = acc;
    __syncthreads();
    for (int s = 16; s > 0; s >>= 1) {
        if (rg < s) f4_add(sred[rg * 16 + cg], sred[(rg + s) * 16 + cg]);
        __syncthreads();
    }
    if (rg == 0) {
        float4 v = sred[cg];
        float4 xr = reinterpret_cast<const float4*>(x)[colbase];
        v.x += xr.x; v.y += xr.y; v.z += xr.z; v.w += xr.w;
        reinterpret_cast<float4*>(d_out)[colbase] = v;
    }
}

extern "C" void kernel_launch(void* const* d_in, const int* in_sizes, int n_in,
                              void* d_out, int out_size) {
    const float* x      = (const float*)d_in[0];
    const float* state1 = (const float*)d_in[1];
    const float* state2 = (const float*)d_in[2];
    const float* ln1_w  = (const float*)d_in[3];
    const float* ln1_b  = (const float*)d_in[4];
    const float* tmx    = (const float*)d_in[5];
    const float* tmw    = (const float*)d_in[6];
    const float* tmk    = (const float*)d_in[7];
    const float* tmv    = (const float*)d_in[8];
    const float* tmr    = (const float*)d_in[9];
    const float* tmg    = (const float*)d_in[10];
    const float* Wmaa1  = (const float*)d_in[11];
    const float* Wmaa2  = (const float*)d_in[12];
    const float* tdec   = (const float*)d_in[13];
    const float* Wd1    = (const float*)d_in[14];
    const float* Wd2    = (const float*)d_in[15];
    const float* faaaa  = (const float*)d_in[16];
    const float* Wr     = (const float*)d_in[17];
    const float* Wk     = (const float*)d_in[18];
    const float* Wv     = (const float*)d_in[19];
    const float* Wg     = (const float*)d_in[20];
    const float* Wo     = (const float*)d_in[21];
    const float* lnxw   = (const float*)d_in[22];
    const float* lnxb   = (const float*)d_in[23];
    float* out = (float*)d_out;

    k2_ln_maa1<<<128, 320>>>(x, state1, ln1_w, ln1_b, tmx, Wmaa1, out);
    k3_mix<<<dim3(16, 5), 256>>>(Wmaa2, tmw, tmk, tmv, tmr, tmg);
    k4_big<<<dim3(64, 5), 512>>>(Wr, Wk, Wv, Wg, Wd1);
    k7_heads<<<64, 256>>>(state2, faaaa, lnxw, lnxb, tdec, Wd2, out);
    k8_wo<<<64, 512>>>(Wo, x, out);
}

// round 7
// speedup vs baseline: 1.3270x; 1.3270x over previous
#include <cuda_runtime.h>
#include <math.h>

#define H 4096
#define HS 64
#define NH 64
#define TM 64
#define TD 128
#define NB 148
#define NT 512

// ---------------- scratch (device globals) ----------------
__device__ float g_xn[H];
__device__ float g_sx[H];
__device__ float g_maa_part[128][5 * TM];
__device__ float g_m[5][H];
__device__ float g_wd1_part[64][TD];
__device__ float g_rkvg[4][H];
__device__ float g_gx[H];

__device__ unsigned long long g_bar = 0ULL;   // monotone barrier counter
__device__ unsigned int g_tickC;              // ticket counters (reset each launch)
__device__ unsigned int g_tickE;

__global__ void k_reset(void) {
    g_tickC = 0u;
    g_tickE = 0u;
}

__device__ __forceinline__ void grid_barrier() {
    __syncthreads();
    if (threadIdx.x == 0) {
        __threadfence();
        unsigned long long ticket = atomicAdd(&g_bar, 1ULL);
        unsigned long long goal = (ticket / NB + 1ULL) * NB;
        while (*((volatile unsigned long long*)&g_bar) < goal) { }
        __threadfence();
    }
    __syncthreads();
}

__device__ __forceinline__ void f4_fma(float4& a, float m, const float4& w) {
    a.x += m * w.x; a.y += m * w.y; a.z += m * w.z; a.w += m * w.w;
}
__device__ __forceinline__ void f4_add(float4& a, const float4& b) {
    a.x += b.x; a.y += b.y; a.z += b.z; a.w += b.w;
}

__global__ __launch_bounds__(NT, 1)
void k_mega(const float* __restrict__ x,
            const float* __restrict__ s1,
            const float* __restrict__ state2,
            const float* __restrict__ ln1_w,
            const float* __restrict__ ln1_b,
            const float* __restrict__ tmx,
            const float* __restrict__ tmw,
            const float* __restrict__ tmk,
            const float* __restrict__ tmv,
            const float* __restrict__ tmr,
            const float* __restrict__ tmg,
            const float* __restrict__ Wmaa1,
            const float* __restrict__ Wmaa2,
            const float* __restrict__ tdec,
            const float* __restrict__ Wd1,
            const float* __restrict__ Wd2,
            const float* __restrict__ faaaa,
            const float* __restrict__ Wr,
            const float* __restrict__ Wk,
            const float* __restrict__ Wv,
            const float* __restrict__ Wg,
            const float* __restrict__ Wo,
            const float* __restrict__ lnxw,
            const float* __restrict__ lnxb,
            float* __restrict__ d_out) {
    __shared__ __align__(16) float sm[4096 + 1024];   // 20 KB scratch
    __shared__ unsigned s_u;
    int t = threadIdx.x;
    int b = blockIdx.x;

    // ================= Phase A: LN stats (redundant) + token shift + maa1 partials ====
    {
        float lsum = 0.f, lsq = 0.f;
        const float4* x4 = reinterpret_cast<const float4*>(x);
#pragma unroll
        for (int i = t; i < 1024; i += NT) {
            float4 v = x4[i];
            lsum += v.x + v.y + v.z + v.w;
            lsq += v.x * v.x + v.y * v.y + v.z * v.z + v.w * v.w;
        }
        sm[t] = lsum; sm[512 + t] = lsq;
        __syncthreads();
        for (int s = 256; s > 0; s >>= 1) {
            if (t < s) { sm[t] += sm[t + s]; sm[512 + t] += sm[512 + t + s]; }
            __syncthreads();
        }
        float mean = sm[0] * (1.0f / H);
        float var = sm[512] * (1.0f / H) - mean * mean;
        float rs = rsqrtf(var + 1e-5f);
        __syncthreads();

        int c = b;                       // 128 chunks of 32 rows; blocks 128+ idle
        if (c < 128) {
            if (t < 32) {
                int i = c * 32 + t;
                float xn = (x[i] - mean) * rs * ln1_w[i] + ln1_b[i];
                float sx = s1[i] - xn;
                g_xn[i] = xn;
                g_sx[i] = sx;
                d_out[H + i] = xn;       // state1_out
                sm[1024 + t] = xn + sx * tmx[i];
            }
            __syncthreads();
            if (t < 320) {
                float acc = 0.f;
#pragma unroll 8
                for (int i = 0; i < 32; i++)
                    acc += sm[1024 + i] * Wmaa1[(size_t)(c * 32 + i) * 320 + t];
                g_maa_part[c][t] = acc;
            }
        }
    }
    grid_barrier();

    // ================= Phase B: mix = tanh(reduce), m = xn + sx*(mix@Wmaa2 + maa) =====
    {
        int u = b;                       // 80 units: 5 s-heads x 16 col-chunks
        if (u < 80) {
            int s5 = u >> 4, chunk = u & 15;
            int tt = t & 63, seg = t >> 6;
            float a = 0.f;
#pragma unroll
            for (int cc = seg * 16; cc < seg * 16 + 16; cc++)
                a += g_maa_part[cc][s5 * 64 + tt];
            sm[t] = a;
            __syncthreads();
            if (t < 64) {
                float m = sm[t];
#pragma unroll
                for (int g2 = 1; g2 < 8; g2++) m += sm[g2 * 64 + t];
                sm[512 + t] = tanhf(m);
            }
            __syncthreads();
            if (t < 256) {
                int hh = chunk * 256 + t;
                float acc = 0.f;
#pragma unroll 8
                for (int e = 0; e < 64; e++)
                    acc += sm[512 + e] * Wmaa2[(size_t)(s5 * 64 + e) * H + hh];
                const float* maa = (s5 == 0) ? tmw : (s5 == 1) ? tmk : (s5 == 2) ? tmv
                                  : (s5 == 3) ? tmr : tmg;
                g_m[s5][hh] = g_xn[hh] + g_sx[hh] * (acc + maa[hh]);
            }
        }
    }
    grid_barrier();

    // ================= Phase C: r/k/v/g direct full-K GEMV (ticket) + Wd1 partials ====
    // units 0..511: (mat = u&3, stripe = u>>2 of 32 cols). units 512..575: Wd1 splits.
    for (;;) {
        __syncthreads();
        if (t == 0) s_u = atomicAdd(&g_tickC, 1u);
        __syncthreads();
        unsigned u = s_u;
        if (u >= 576u) break;
        if (u < 512u) {
            int mat = u & 3;
            int stripe = u >> 2;         // 0..127
            const float* vec = (mat == 0) ? g_m[3] : (mat == 1) ? g_m[1]
                              : (mat == 2) ? g_m[2] : g_m[4];
            const float* W = (mat == 0) ? Wr : (mat == 1) ? Wk : (mat == 2) ? Wv : Wg;
            float4* sv4 = reinterpret_cast<float4*>(sm);
            const float4* v4 = reinterpret_cast<const float4*>(vec);
#pragma unroll
            for (int i = t; i < 1024; i += NT) sv4[i] = v4[i];
            __syncthreads();
            const float4* W4 = reinterpret_cast<const float4*>(W);
            int cg = t & 7, rg = t >> 3;          // 8 f4-cols x 64 row-groups
            int colbase = stripe * 8 + cg;
            float4 acc = make_float4(0.f, 0.f, 0.f, 0.f);
#pragma unroll 8
            for (int i = 0; i < 64; i++) {
                int row = i * 64 + rg;
                f4_fma(acc, sm[row], W4[(size_t)row * 1024 + colbase]);
            }
            // reduce over rg: warp covers 4 rgs (t bits 3,4), then 16 warps in smem
            acc.x += __shfl_xor_sync(0xffffffffu, acc.x, 8);
            acc.y += __shfl_xor_sync(0xffffffffu, acc.y, 8);
            acc.z += __shfl_xor_sync(0xffffffffu, acc.z, 8);
            acc.w += __shfl_xor_sync(0xffffffffu, acc.w, 8);
            acc.x += __shfl_xor_sync(0xffffffffu, acc.x, 16);
            acc.y += __shfl_xor_sync(0xffffffffu, acc.y, 16);
            acc.z += __shfl_xor_sync(0xffffffffu, acc.z, 16);
            acc.w += __shfl_xor_sync(0xffffffffu, acc.w, 16);
            float4* sred = reinterpret_cast<float4*>(sm + 4096);
            int w = t >> 5;
            if ((t & 31) < 8) sred[w * 8 + cg] = acc;
            __syncthreads();
            if (t < 8) {
                float4 a = sred[t];
#pragma unroll
                for (int w2 = 1; w2 < 16; w2++) f4_add(a, sred[w2 * 8 + t]);
                if (mat == 3) {
                    a.x = a.x / (1.0f + expf(-a.x));
                    a.y = a.y / (1.0f + expf(-a.y));
                    a.z = a.z / (1.0f + expf(-a.z));
                    a.w = a.w / (1.0f + expf(-a.w));
                }
                reinterpret_cast<float4*>(g_rkvg[mat])[stripe * 8 + t] = a;
            }
        } else {
            int split = (int)u - 512;    // 64 rows
            int col = t & 127, seg = t >> 7;   // 4 segs x 16 rows
            const float* vrow = g_m[0] + split * 64 + seg * 16;
            float acc = 0.f;
#pragma unroll
            for (int i = 0; i < 16; i++)
                acc += vrow[i] * Wd1[(size_t)(split * 64 + seg * 16 + i) * TD + col];
            sm[t] = acc;
            __syncthreads();
            if (t < TD)
                g_wd1_part[split][t] = sm[t] + sm[t + 128] + sm[t + 256] + sm[t + 384];
        }
    }
    grid_barrier();

    // ================= Phase D: decay + heads + instnorm + gate (blocks 0..63) ========
    {
        int h = b;
        if (h < 64) {
            int base = h * HS;
            // wd1 reduce -> tanh
            {
                int col = t & 127, sg = t >> 7;    // 4 segs x 16 splits
                float a = 0.f;
#pragma unroll
                for (int s = sg * 16; s < sg * 16 + 16; s++)
                    a += g_wd1_part[s][col];
                sm[t] = a;
            }
            __syncthreads();
            if (t < TD)
                sm[512 + t] = tanhf(sm[t] + sm[t + 128] + sm[t + 256] + sm[t + 384]);
            __syncthreads();
            // Wd2 stripe for this head's 64 cols
            {
                int d = t & 63, sg = t >> 6;       // 8 segs x 16 e
                float a = 0.f;
#pragma unroll
                for (int e = sg * 16; e < sg * 16 + 16; e++)
                    a += sm[512 + e] * Wd2[(size_t)e * H + base + d];
                sm[640 + t] = a;
            }
            __syncthreads();
            // r/k/v/td + prod
            float* r_s = sm + 1152;
            float* k_s = sm + 1216;
            float* v_s = sm + 1280;
            float* td_s = sm + 1344;
            float* prod = sm + 1408;
            float* part = sm + 1472;   // 512
            float* red = sm + 1984;
            float* red2 = sm + 2048;
            if (t < 64) {
                float s = sm[640 + t] + sm[640 + 64 + t] + sm[640 + 128 + t] + sm[640 + 192 + t]
                        + sm[640 + 256 + t] + sm[640 + 320 + t] + sm[640 + 384 + t] + sm[640 + 448 + t];
                td_s[t] = expf(-expf(tdec[base + t] + s));
                float rv = g_rkvg[0][base + t];
                float kv = g_rkvg[1][base + t];
                r_s[t] = rv;
                k_s[t] = kv;
                v_s[t] = g_rkvg[2][base + t];
                prod[t] = rv * kv * faaaa[base + t];
            }
            __syncthreads();
            if (t < 32) prod[t] += prod[t + 32];
            __syncthreads();
            if (t < 16) prod[t] += prod[t + 16];
            __syncthreads();
            if (t < 8) prod[t] += prod[t + 8];
            __syncthreads();
            if (t < 4) prod[t] += prod[t + 4];
            __syncthreads();
            if (t < 2) prod[t] += prod[t + 2];
            __syncthreads();
            if (t == 0) prod[0] += prod[1];
            __syncthreads();
            float dot1 = prod[0];

            int d = t & 63, q = t >> 6;            // 8 groups x 8 kk
            const float* s2 = state2 + (size_t)h * HS * HS;
            float* s2o = d_out + 2 * H + (size_t)h * HS * HS;
            float vv = v_s[d];
            float acc = 0.f;
#pragma unroll
            for (int kk = q * 8; kk < q * 8 + 8; kk++) {
                float s2v = s2[kk * HS + d];
                acc += r_s[kk] * s2v;
                s2o[kk * HS + d] = k_s[kk] * vv + s2v * td_s[kk];
            }
            part[q * 64 + d] = acc;
            __syncthreads();

            if (t < 64) {
                float out_d = v_s[t] * dot1;
#pragma unroll
                for (int q2 = 0; q2 < 8; q2++) out_d += part[q2 * 64 + t];
                red[t] = out_d;
                red2[t] = out_d * out_d;
                part[t] = out_d;   // stash
            }
            __syncthreads();
            if (t < 32) { red[t] += red[t + 32]; red2[t] += red2[t + 32]; }
            __syncthreads();
            if (t < 16) { red[t] += red[t + 16]; red2[t] += red2[t + 16]; }
            __syncthreads();
            if (t < 8) { red[t] += red[t + 8]; red2[t] += red2[t + 8]; }
            __syncthreads();
            if (t < 4) { red[t] += red[t + 4]; red2[t] += red2[t + 4]; }
            __syncthreads();
            if (t < 2) { red[t] += red[t + 2]; red2[t] += red2[t + 2]; }
            __syncthreads();
            if (t == 0) { red[0] += red[1]; red2[0] += red2[1]; }
            __syncthreads();
            if (t < 64) {
                float mean = red[0] * (1.0f / HS);
                float var = red2[0] * (1.0f / HS) - mean * mean;
                float o = (part[t] - mean) * rsqrtf(var + 1e-5f) * lnxw[base + t] + lnxb[base + t];
                g_gx[base + t] = o * g_rkvg[3][base + t];
            }
        }
    }
    grid_barrier();

    // ================= Phase E: Wo direct full-K GEMV + residual (ticket) =============
    // 256 units of 16 cols (4 f4 cols).
    for (;;) {
        __syncthreads();
        if (t == 0) s_u = atomicAdd(&g_tickE, 1u);
        __syncthreads();
        unsigned u = s_u;
        if (u >= 256u) break;
        float4* sv4 = reinterpret_cast<float4*>(sm);
        const float4* gx4 = reinterpret_cast<const float4*>(g_gx);
#pragma unroll
        for (int i = t; i < 1024; i += NT) sv4[i] = gx4[i];
        __syncthreads();
        const float4* W4 = reinterpret_cast<const float4*>(Wo);
        int cg = t & 3, rg = t >> 2;               // 4 f4-cols x 128 row-groups
        int colbase = u * 4 + cg;
        float4 acc = make_float4(0.f, 0.f, 0.f, 0.f);
#pragma unroll 8
        for (int i = 0; i < 32; i++) {
            int row = i * 128 + rg;
            f4_fma(acc, sm[row], W4[(size_t)row * 1024 + colbase]);
        }
        // reduce over rg: warp covers 8 rgs (t bits 2,3,4)
        acc.x += __shfl_xor_sync(0xffffffffu, acc.x, 4);
        acc.y += __shfl_xor_sync(0xffffffffu, acc.y, 4);
        acc.z += __shfl_xor_sync(0xffffffffu, acc.z, 4);
        acc.w += __shfl_xor_sync(0xffffffffu, acc.w, 4);
        acc.x += __shfl_xor_sync(0xffffffffu, acc.x, 8);
        acc.y += __shfl_xor_sync(0xffffffffu, acc.y, 8);
        acc.z += __shfl_xor_sync(0xffffffffu, acc.z, 8);
        acc.w += __shfl_xor_sync(0xffffffffu, acc.w, 8);
        acc.x += __shfl_xor_sync(0xffffffffu, acc.x, 16);
        acc.y += __shfl_xor_sync(0xffffffffu, acc.y, 16);
        acc.z += __shfl_xor_sync(0xffffffffu, acc.z, 16);
        acc.w += __shfl_xor_sync(0xffffffffu, acc.w, 16);
        float4* sred = reinterpret_cast<float4*>(sm + 4096);
        int w = t >> 5;
        if ((t & 31) < 4) sred[w * 4 + cg] = acc;
        __syncthreads();
        if (t < 4) {
            float4 a = sred[t];
#pragma unroll
            for (int w2 = 1; w2 < 16; w2++) f4_add(a, sred[w2 * 4 + t]);
            float4 xr = reinterpret_cast<const float4*>(x)[u * 4 + t];
            a.x += xr.x; a.y += xr.y; a.z += xr.z; a.w += xr.w;
            reinterpret_cast<float4*>(d_out)[u * 4 + t] = a;
        }
    }
}

extern "C" void kernel_launch(void* const* d_in, const int* in_sizes, int n_in,
                              void* d_out, int out_size) {
    const float* x      = (const float*)d_in[0];
    const float* state1 = (const float*)d_in[1];
    const float* state2 = (const float*)d_in[2];
    const float* ln1_w  = (const float*)d_in[3];
    const float* ln1_b  = (const float*)d_in[4];
    const float* tmx    = (const float*)d_in[5];
    const float* tmw    = (const float*)d_in[6];
    const float* tmk    = (const float*)d_in[7];
    const float* tmv    = (const float*)d_in[8];
    const float* tmr    = (const float*)d_in[9];
    const float* tmg    = (const float*)d_in[10];
    const float* Wmaa1  = (const float*)d_in[11];
    const float* Wmaa2  = (const float*)d_in[12];
    const float* tdec   = (const float*)d_in[13];
    const float* Wd1    = (const float*)d_in[14];
    const float* Wd2    = (const float*)d_in[15];
    const float* faaaa  = (const float*)d_in[16];
    const float* Wr     = (const float*)d_in[17];
    const float* Wk     = (const float*)d_in[18];
    const float* Wv     = (const float*)d_in[19];
    const float* Wg     = (const float*)d_in[20];
    const float* Wo     = (const float*)d_in[21];
    const float* lnxw   = (const float*)d_in[22];
    const float* lnxb   = (const float*)d_in[23];
    float* out = (float*)d_out;

    k_reset<<<1, 32>>>();
    k_mega<<<NB, NT>>>(x, state1, state2, ln1_w, ln1_b, tmx, tmw, tmk, tmv, tmr, tmg,
                       Wmaa1, Wmaa2, tdec, Wd1, Wd2, faaaa, Wr, Wk, Wv, Wg, Wo,
                       lnxw, lnxb, out);
}

// round 8
// speedup vs baseline: 1.4234x; 1.0726x over previous
#include <cuda_runtime.h>
#include <math.h>

#define H 4096
#define HS 64
#define NH 64
#define TM 64
#define TD 128
#define GRID 296
#define NT 512

// ---------------- scratch (device globals) ----------------
__device__ float g_xn[H];
__device__ float g_sx[H];
__device__ float g_maa_part[128][5 * TM];
__device__ float g_m[5][H];
__device__ float g_wd1_part[64][TD];
__device__ float g_rkvg[4][H];
__device__ float g_gx[H];

__device__ unsigned long long g_bar = 0ULL;   // monotone barrier counter
__device__ unsigned int g_tickC;              // ticket counters (reset each launch)
__device__ unsigned int g_tickE;

__global__ void k_reset(void) {
    g_tickC = 0u;
    g_tickE = 0u;
}

__device__ __forceinline__ void grid_barrier() {
    __syncthreads();
    if (threadIdx.x == 0) {
        __threadfence();
        unsigned long long ticket = atomicAdd(&g_bar, 1ULL);
        unsigned long long goal = (ticket / GRID + 1ULL) * GRID;
        while (*((volatile unsigned long long*)&g_bar) < goal) { }
        __threadfence();
    }
    __syncthreads();
}

__device__ __forceinline__ void f4_fma(float4& a, float m, const float4& w) {
    a.x += m * w.x; a.y += m * w.y; a.z += m * w.z; a.w += m * w.w;
}
__device__ __forceinline__ void f4_add(float4& a, const float4& b) {
    a.x += b.x; a.y += b.y; a.z += b.z; a.w += b.w;
}

__global__ __launch_bounds__(NT, 2)
void k_mega(const float* __restrict__ x,
            const float* __restrict__ s1,
            const float* __restrict__ state2,
            const float* __restrict__ ln1_w,
            const float* __restrict__ ln1_b,
            const float* __restrict__ tmx,
            const float* __restrict__ tmw,
            const float* __restrict__ tmk,
            const float* __restrict__ tmv,
            const float* __restrict__ tmr,
            const float* __restrict__ tmg,
            const float* __restrict__ Wmaa1,
            const float* __restrict__ Wmaa2,
            const float* __restrict__ tdec,
            const float* __restrict__ Wd1,
            const float* __restrict__ Wd2,
            const float* __restrict__ faaaa,
            const float* __restrict__ Wr,
            const float* __restrict__ Wk,
            const float* __restrict__ Wv,
            const float* __restrict__ Wg,
            const float* __restrict__ Wo,
            const float* __restrict__ lnxw,
            const float* __restrict__ lnxb,
            float* __restrict__ d_out) {
    __shared__ __align__(16) float sm[4096 + 1024];   // 20 KB scratch
    __shared__ unsigned s_u;
    int t = threadIdx.x;
    int b = blockIdx.x;

    // ================= Phase A: LN stats (redundant) + token shift + maa1 partials ====
    {
        float lsum = 0.f, lsq = 0.f;
        const float4* x4 = reinterpret_cast<const float4*>(x);
#pragma unroll
        for (int i = t; i < 1024; i += NT) {
            float4 v = x4[i];
            lsum += v.x + v.y + v.z + v.w;
            lsq += v.x * v.x + v.y * v.y + v.z * v.z + v.w * v.w;
        }
        sm[t] = lsum; sm[512 + t] = lsq;
        __syncthreads();
        for (int s = 256; s > 0; s >>= 1) {
            if (t < s) { sm[t] += sm[t + s]; sm[512 + t] += sm[512 + t + s]; }
            __syncthreads();
        }
        float mean = sm[0] * (1.0f / H);
        float var = sm[512] * (1.0f / H) - mean * mean;
        float rs = rsqrtf(var + 1e-5f);
        __syncthreads();

        int c = b;                       // 128 chunks of 32 rows; blocks 128+ idle
        if (c < 128) {
            if (t < 32) {
                int i = c * 32 + t;
                float xn = (x[i] - mean) * rs * ln1_w[i] + ln1_b[i];
                float sx = s1[i] - xn;
                g_xn[i] = xn;
                g_sx[i] = sx;
                d_out[H + i] = xn;       // state1_out
                sm[1024 + t] = xn + sx * tmx[i];
            }
            __syncthreads();
            if (t < 320) {
                float acc = 0.f;
#pragma unroll 8
                for (int i = 0; i < 32; i++)
                    acc += sm[1024 + i] * Wmaa1[(size_t)(c * 32 + i) * 320 + t];
                g_maa_part[c][t] = acc;
            }
        }
    }
    grid_barrier();

    // ================= Phase B: mix = tanh(reduce), m = xn + sx*(mix@Wmaa2 + maa) =====
    {
        int u = b;                       // 80 units: 5 s-heads x 16 col-chunks
        if (u < 80) {
            int s5 = u >> 4, chunk = u & 15;
            int tt = t & 63, seg = t >> 6;
            float a = 0.f;
#pragma unroll
            for (int cc = seg * 16; cc < seg * 16 + 16; cc++)
                a += g_maa_part[cc][s5 * 64 + tt];
            sm[t] = a;
            __syncthreads();
            if (t < 64) {
                float m = sm[t];
#pragma unroll
                for (int g2 = 1; g2 < 8; g2++) m += sm[g2 * 64 + t];
                sm[512 + t] = tanhf(m);
            }
            __syncthreads();
            if (t < 256) {
                int hh = chunk * 256 + t;
                float acc = 0.f;
#pragma unroll 8
                for (int e = 0; e < 64; e++)
                    acc += sm[512 + e] * Wmaa2[(size_t)(s5 * 64 + e) * H + hh];
                const float* maa = (s5 == 0) ? tmw : (s5 == 1) ? tmk : (s5 == 2) ? tmv
                                  : (s5 == 3) ? tmr : tmg;
                g_m[s5][hh] = g_xn[hh] + g_sx[hh] * (acc + maa[hh]);
            }
        }
    }
    grid_barrier();

    // ================= Phase C: r/k/v/g direct full-K GEMV (ticket) + Wd1 partials ====
    // units 0..511: (mat = u&3, stripe = u>>2 of 32 cols). units 512..575: Wd1 splits.
    for (;;) {
        __syncthreads();
        if (t == 0) s_u = atomicAdd(&g_tickC, 1u);
        __syncthreads();
        unsigned u = s_u;
        if (u >= 576u) break;
        if (u < 512u) {
            int mat = u & 3;
            int stripe = u >> 2;         // 0..127
            const float* vec = (mat == 0) ? g_m[3] : (mat == 1) ? g_m[1]
                              : (mat == 2) ? g_m[2] : g_m[4];
            const float* W = (mat == 0) ? Wr : (mat == 1) ? Wk : (mat == 2) ? Wv : Wg;
            float4* sv4 = reinterpret_cast<float4*>(sm);
            const float4* v4 = reinterpret_cast<const float4*>(vec);
#pragma unroll
            for (int i = t; i < 1024; i += NT) sv4[i] = v4[i];
            __syncthreads();
            const float4* W4 = reinterpret_cast<const float4*>(W);
            int cg = t & 7, rg = t >> 3;          // 8 f4-cols x 64 row-groups
            int colbase = stripe * 8 + cg;
            float4 acc0 = make_float4(0.f, 0.f, 0.f, 0.f);
            float4 acc1 = make_float4(0.f, 0.f, 0.f, 0.f);
#pragma unroll 4
            for (int i = 0; i < 32; i++) {
                int r0 = i * 64 + rg;
                int r1 = (i + 32) * 64 + rg;
                f4_fma(acc0, sm[r0], W4[(size_t)r0 * 1024 + colbase]);
                f4_fma(acc1, sm[r1], W4[(size_t)r1 * 1024 + colbase]);
            }
            f4_add(acc0, acc1);
            // reduce over rg: warp covers 4 rgs (t bits 3,4), then 16 warps in smem
            acc0.x += __shfl_xor_sync(0xffffffffu, acc0.x, 8);
            acc0.y += __shfl_xor_sync(0xffffffffu, acc0.y, 8);
            acc0.z += __shfl_xor_sync(0xffffffffu, acc0.z, 8);
            acc0.w += __shfl_xor_sync(0xffffffffu, acc0.w, 8);
            acc0.x += __shfl_xor_sync(0xffffffffu, acc0.x, 16);
            acc0.y += __shfl_xor_sync(0xffffffffu, acc0.y, 16);
            acc0.z += __shfl_xor_sync(0xffffffffu, acc0.z, 16);
            acc0.w += __shfl_xor_sync(0xffffffffu, acc0.w, 16);
            float4* sred = reinterpret_cast<float4*>(sm + 4096);
            int w = t >> 5;
            if ((t & 31) < 8) sred[w * 8 + cg] = acc0;
            __syncthreads();
            if (t < 8) {
                float4 a = sred[t];
#pragma unroll
                for (int w2 = 1; w2 < 16; w2++) f4_add(a, sred[w2 * 8 + t]);
                if (mat == 3) {
                    a.x = a.x / (1.0f + expf(-a.x));
                    a.y = a.y / (1.0f + expf(-a.y));
                    a.z = a.z / (1.0f + expf(-a.z));
                    a.w = a.w / (1.0f + expf(-a.w));
                }
                reinterpret_cast<float4*>(g_rkvg[mat])[stripe * 8 + t] = a;
            }
        } else {
            int split = (int)u - 512;    // 64 rows
            int col = t & 127, seg = t >> 7;   // 4 segs x 16 rows
            const float* vrow = g_m[0] + split * 64 + seg * 16;
            float acc = 0.f;
#pragma unroll
            for (int i = 0; i < 16; i++)
                acc += vrow[i] * Wd1[(size_t)(split * 64 + seg * 16 + i) * TD + col];
            sm[t] = acc;
            __syncthreads();
            if (t < TD)
                g_wd1_part[split][t] = sm[t] + sm[t + 128] + sm[t + 256] + sm[t + 384];
        }
    }
    grid_barrier();

    // ================= Phase D: decay + heads + instnorm + gate (blocks 0..63) ========
    {
        int h = b;
        if (h < 64) {
            int base = h * HS;
            // wd1 reduce -> tanh
            {
                int col = t & 127, sg = t >> 7;    // 4 segs x 16 splits
                float a = 0.f;
#pragma unroll
                for (int s = sg * 16; s < sg * 16 + 16; s++)
                    a += g_wd1_part[s][col];
                sm[t] = a;
            }
            __syncthreads();
            if (t < TD)
                sm[512 + t] = tanhf(sm[t] + sm[t + 128] + sm[t + 256] + sm[t + 384]);
            __syncthreads();
            // Wd2 stripe for this head's 64 cols
            {
                int d = t & 63, sg = t >> 6;       // 8 segs x 16 e
                float a = 0.f;
#pragma unroll
                for (int e = sg * 16; e < sg * 16 + 16; e++)
                    a += sm[512 + e] * Wd2[(size_t)e * H + base + d];
                sm[640 + t] = a;
            }
            __syncthreads();
            float* r_s = sm + 1152;
            float* k_s = sm + 1216;
            float* v_s = sm + 1280;
            float* td_s = sm + 1344;
            float* prod = sm + 1408;
            float* part = sm + 1472;   // 512
            float* red = sm + 1984;
            float* red2 = sm + 2048;
            if (t < 64) {
                float s = sm[640 + t] + sm[640 + 64 + t] + sm[640 + 128 + t] + sm[640 + 192 + t]
                        + sm[640 + 256 + t] + sm[640 + 320 + t] + sm[640 + 384 + t] + sm[640 + 448 + t];
                td_s[t] = expf(-expf(tdec[base + t] + s));
                float rv = g_rkvg[0][base + t];
                float kv = g_rkvg[1][base + t];
                r_s[t] = rv;
                k_s[t] = kv;
                v_s[t] = g_rkvg[2][base + t];
                prod[t] = rv * kv * faaaa[base + t];
            }
            __syncthreads();
            if (t < 32) prod[t] += prod[t + 32];
            __syncthreads();
            if (t < 16) prod[t] += prod[t + 16];
            __syncthreads();
            if (t < 8) prod[t] += prod[t + 8];
            __syncthreads();
            if (t < 4) prod[t] += prod[t + 4];
            __syncthreads();
            if (t < 2) prod[t] += prod[t + 2];
            __syncthreads();
            if (t == 0) prod[0] += prod[1];
            __syncthreads();
            float dot1 = prod[0];

            int d = t & 63, q = t >> 6;            // 8 groups x 8 kk
            const float* s2 = state2 + (size_t)h * HS * HS;
            float* s2o = d_out + 2 * H + (size_t)h * HS * HS;
            float vv = v_s[d];
            float acc = 0.f;
#pragma unroll
            for (int kk = q * 8; kk < q * 8 + 8; kk++) {
                float s2v = s2[kk * HS + d];
                acc += r_s[kk] * s2v;
                s2o[kk * HS + d] = k_s[kk] * vv + s2v * td_s[kk];
            }
            part[q * 64 + d] = acc;
            __syncthreads();

            if (t < 64) {
                float out_d = v_s[t] * dot1;
#pragma unroll
                for (int q2 = 0; q2 < 8; q2++) out_d += part[q2 * 64 + t];
                red[t] = out_d;
                red2[t] = out_d * out_d;
                part[t] = out_d;   // stash
            }
            __syncthreads();
            if (t < 32) { red[t] += red[t + 32]; red2[t] += red2[t + 32]; }
            __syncthreads();
            if (t < 16) { red[t] += red[t + 16]; red2[t] += red2[t + 16]; }
            __syncthreads();
            if (t < 8) { red[t] += red[t + 8]; red2[t] += red2[t + 8]; }
            __syncthreads();
            if (t < 4) { red[t] += red[t + 4]; red2[t] += red2[t + 4]; }
            __syncthreads();
            if (t < 2) { red[t] += red[t + 2]; red2[t] += red2[t + 2]; }
            __syncthreads();
            if (t == 0) { red[0] += red[1]; red2[0] += red2[1]; }
            __syncthreads();
            if (t < 64) {
                float mean = red[0] * (1.0f / HS);
                float var = red2[0] * (1.0f / HS) - mean * mean;
                float o = (part[t] - mean) * rsqrtf(var + 1e-5f) * lnxw[base + t] + lnxb[base + t];
                g_gx[base + t] = o * g_rkvg[3][base + t];
            }
        }
    }
    grid_barrier();

    // ================= Phase E: Wo direct full-K GEMV + residual (ticket) =============
    // 256 units of 16 cols (4 f4 cols).
    for (;;) {
        __syncthreads();
        if (t == 0) s_u = atomicAdd(&g_tickE, 1u);
        __syncthreads();
        unsigned u = s_u;
        if (u >= 256u) break;
        float4* sv4 = reinterpret_cast<float4*>(sm);
        const float4* gx4 = reinterpret_cast<const float4*>(g_gx);
#pragma unroll
        for (int i = t; i < 1024; i += NT) sv4[i] = gx4[i];
        __syncthreads();
        const float4* W4 = reinterpret_cast<const float4*>(Wo);
        int cg = t & 3, rg = t >> 2;               // 4 f4-cols x 128 row-groups
        int colbase = u * 4 + cg;
        float4 acc0 = make_float4(0.f, 0.f, 0.f, 0.f);
        float4 acc1 = make_float4(0.f, 0.f, 0.f, 0.f);
#pragma unroll 4
        for (int i = 0; i < 16; i++) {
            int r0 = i * 128 + rg;
            int r1 = (i + 16) * 128 + rg;
            f4_fma(acc0, sm[r0], W4[(size_t)r0 * 1024 + colbase]);
            f4_fma(acc1, sm[r1], W4[(size_t)r1 * 1024 + colbase]);
        }
        f4_add(acc0, acc1);
        // reduce over rg: warp covers 8 rgs (t bits 2,3,4)
        acc0.x += __shfl_xor_sync(0xffffffffu, acc0.x, 4);
        acc0.y += __shfl_xor_sync(0xffffffffu, acc0.y, 4);
        acc0.z += __shfl_xor_sync(0xffffffffu, acc0.z, 4);
        acc0.w += __shfl_xor_sync(0xffffffffu, acc0.w, 4);
        acc0.x += __shfl_xor_sync(0xffffffffu, acc0.x, 8);
        acc0.y += __shfl_xor_sync(0xffffffffu, acc0.y, 8);
        acc0.z += __shfl_xor_sync(0xffffffffu, acc0.z, 8);
        acc0.w += __shfl_xor_sync(0xffffffffu, acc0.w, 8);
        acc0.x += __shfl_xor_sync(0xffffffffu, acc0.x, 16);
        acc0.y += __shfl_xor_sync(0xffffffffu, acc0.y, 16);
        acc0.z += __shfl_xor_sync(0xffffffffu, acc0.z, 16);
        acc0.w += __shfl_xor_sync(0xffffffffu, acc0.w, 16);
        float4* sred = reinterpret_cast<float4*>(sm + 4096);
        int w = t >> 5;
        if ((t & 31) < 4) sred[w * 4 + cg] = acc0;
        __syncthreads();
        if (t < 4) {
            float4 a = sred[t];
#pragma unroll
            for (int w2 = 1; w2 < 16; w2++) f4_add(a, sred[w2 * 4 + t]);
            float4 xr = reinterpret_cast<const float4*>(x)[u * 4 + t];
            a.x += xr.x; a.y += xr.y; a.z += xr.z; a.w += xr.w;
            reinterpret_cast<float4*>(d_out)[u * 4 + t] = a;
        }
    }
}

extern "C" void kernel_launch(void* const* d_in, const int* in_sizes, int n_in,
                              void* d_out, int out_size) {
    const float* x      = (const float*)d_in[0];
    const float* state1 = (const float*)d_in[1];
    const float* state2 = (const float*)d_in[2];
    const float* ln1_w  = (const float*)d_in[3];
    const float* ln1_b  = (const float*)d_in[4];
    const float* tmx    = (const float*)d_in[5];
    const float* tmw    = (const float*)d_in[6];
    const float* tmk    = (const float*)d_in[7];
    const float* tmv    = (const float*)d_in[8];
    const float* tmr    = (const float*)d_in[9];
    const float* tmg    = (const float*)d_in[10];
    const float* Wmaa1  = (const float*)d_in[11];
    const float* Wmaa2  = (const float*)d_in[12];
    const float* tdec   = (const float*)d_in[13];
    const float* Wd1    = (const float*)d_in[14];
    const float* Wd2    = (const float*)d_in[15];
    const float* faaaa  = (const float*)d_in[16];
    const float* Wr     = (const float*)d_in[17];
    const float* Wk     = (const float*)d_in[18];
    const float* Wv     = (const float*)d_in[19];
    const float* Wg     = (const float*)d_in[20];
    const float* Wo     = (const float*)d_in[21];
    const float* lnxw   = (const float*)d_in[22];
    const float* lnxb   = (const float*)d_in[23];
    float* out = (float*)d_out;

    k_reset<<<1, 32>>>();
    k_mega<<<GRID, NT>>>(x, state1, state2, ln1_w, ln1_b, tmx, tmw, tmk, tmv, tmr, tmg,
                         Wmaa1, Wmaa2, tdec, Wd1, Wd2, faaaa, Wr, Wk, Wv, Wg, Wo,
                         lnxw, lnxb, out);
}